// round 14
// baseline (speedup 1.0000x reference)
#include <cuda_runtime.h>
#include <cstdint>

#define TT 2048
#define BB 512
#define KK 8
#define DD 32
#define DT_F 0.05f
#define SQDT_F 0.22360679774997896f  /* sqrt(0.05) */

typedef unsigned long long u64;

// Duplicated normalized weights: per (t,b), 16 floats (w_k, w_k) for k=0..7.
__device__ float g_wn2[(size_t)TT * BB * 16];

// ---------- f32x2 helpers ----------
__device__ __forceinline__ u64 add2(u64 a, u64 b) {
    u64 d; asm("add.rn.f32x2 %0,%1,%2;" : "=l"(d) : "l"(a), "l"(b)); return d;
}
__device__ __forceinline__ void ffma2(u64& d, u64 a, u64 b) {
    asm("fma.rn.f32x2 %0,%1,%2,%3;" : "=l"(d) : "l"(a), "l"(b), "l"(d));
}
__device__ __forceinline__ u64 ffma2_v(u64 a, u64 b, u64 c) {
    u64 d; asm("fma.rn.f32x2 %0,%1,%2,%3;" : "=l"(d) : "l"(a), "l"(b), "l"(c)); return d;
}
__device__ __forceinline__ u64 mul2(u64 a, u64 b) {
    u64 d; asm("mul.rn.f32x2 %0,%1,%2;" : "=l"(d) : "l"(a), "l"(b)); return d;
}
__device__ __forceinline__ u64 pack2(float lo, float hi) {
    u64 v; asm("mov.b64 %0,{%1,%2};" : "=l"(v) : "f"(lo), "f"(hi)); return v;
}
// register-alias extraction (no mov.b64 round trip)
__device__ __forceinline__ float lo2(u64 v) { return __uint_as_float((unsigned)v); }
__device__ __forceinline__ float hi2(u64 v) { return __uint_as_float((unsigned)(v >> 32)); }

// ---------- Kernel 1: normalized weights, duplicated pairs ----------
__global__ void __launch_bounds__(256) norm_kernel(const float* __restrict__ s_probs) {
    int idx = blockIdx.x * blockDim.x + threadIdx.x;  // (t,b) pair
    if (idx < TT * BB) {
        const float4* p = (const float4*)(s_probs + (size_t)idx * KK);
        float4 a = p[0];
        float4 b = p[1];
        float s = ((a.x + a.y) + (a.z + a.w)) + ((b.x + b.y) + (b.z + b.w));
        float r = 1.0f / s;
        float4* o = (float4*)(g_wn2 + (size_t)idx * 16);
        o[0] = make_float4(a.x * r, a.x * r, a.y * r, a.y * r);
        o[1] = make_float4(a.z * r, a.z * r, a.w * r, a.w * r);
        o[2] = make_float4(b.x * r, b.x * r, b.y * r, b.y * r);
        o[3] = make_float4(b.z * r, b.z * r, b.w * r, b.w * r);
    }
}

// ---------- Kernel 2: one CTA (64 thr = 2 warps) per batch (R4 shape) ----------
// Lane i of warp wp owns row i of A_{4wp+kk}, kk=0..3, pre-scaled by dt.
// Packed f32x2 epilogue end-to-end; single-float cross-warp exchange.
__global__ void __launch_bounds__(64, 4) sde_main(
    const float* __restrict__ z0,
    const float* __restrict__ noise,
    const float* __restrict__ A_s,
    const float* __restrict__ b_s,
    const float* __restrict__ Q_chol,
    float* __restrict__ ys)
{
    const int b    = blockIdx.x;
    const int tid  = threadIdx.x;
    const int w    = tid >> 5;       // 0 or 1
    const int lane = tid & 31;       // row i
    const int kb   = w * 4;          // k base

    __shared__ __align__(16) float zbuf[2][DD];     // [warp][row] private z copies
    __shared__ float pbuf[2][2][DD];                // [parity][warp][row] v exchange

    // ---- A rows -> registers as f32x2 pairs, pre-scaled by dt ----
    u64 A[4][16];
    u64 binit[4], Q2[4];
#pragma unroll
    for (int kk = 0; kk < 4; kk++) {
        const float4* r = (const float4*)(A_s + (size_t)((kb + kk) * DD + lane) * DD);
#pragma unroll
        for (int q = 0; q < 8; q++) {
            float4 v = r[q];
            A[kk][2 * q]     = pack2(DT_F * v.x, DT_F * v.y);
            A[kk][2 * q + 1] = pack2(DT_F * v.z, DT_F * v.w);
        }
        binit[kk] = pack2(DT_F * b_s[(kb + kk) * DD + lane], 0.0f);
        float qs  = SQDT_F * Q_chol[(kb + kk) * DD + lane];
        Q2[kk]    = pack2(qs, qs);
    }

    // ---- z init ----
    float zreg = z0[(size_t)b * DD + lane];
    zbuf[w][lane] = zreg;

    // stream pointers
    const ulonglong2* wq = (const ulonglong2*)g_wn2;    // (t*BB+b)*4 + w*2
    const float*      np = noise + (size_t)b * DD + lane;
    float*            yp = ys    + (size_t)b * DD + lane;

    // ---- prefetch: load W pairs (4 u64) + dw for step ts ----
    auto pf = [&](int ts, u64 (&W)[4], float& dw) {
        if (ts >= TT) ts = TT - 1;
        size_t base = ((size_t)ts * BB + b) * 4 + (size_t)(w * 2);
        ulonglong2 q0 = __ldg(&wq[base]);
        ulonglong2 q1 = __ldg(&wq[base + 1]);
        W[0] = q0.x; W[1] = q0.y; W[2] = q1.x; W[3] = q1.y;
        dw = __ldg(&np[(size_t)ts * (BB * DD)]);
    };

    // ---- one Euler step ----
    auto step = [&](int si, const u64 (&W)[4], float dw) {
        const int par = si & 1;
        const ulonglong2* zv = (const ulonglong2*)(&zbuf[w][0]);

        u64 ca[4], cb[4];
        {
            ulonglong2 z2 = zv[0];
#pragma unroll
            for (int kk = 0; kk < 4; kk++) {
                ca[kk] = ffma2_v(A[kk][0], z2.x, binit[kk]);  // bias folded, no init movs
                cb[kk] = mul2(A[kk][1], z2.y);
            }
        }
#pragma unroll
        for (int jj = 1; jj < 8; jj++) {
            ulonglong2 z2 = zv[jj];                           // LDS.128 broadcast
#pragma unroll
            for (int kk = 0; kk < 4; kk++) {
                ffma2(ca[kk], A[kk][2 * jj],     z2.x);
                ffma2(cb[kk], A[kk][2 * jj + 1], z2.y);
            }
        }

        // packed weighted k-combine: drift halves and diffusion in f32x2
        u64 P  = mul2(W[0], add2(ca[0], cb[0]));
        ffma2(P,  W[1], add2(ca[1], cb[1]));
        ffma2(P,  W[2], add2(ca[2], cb[2]));
        ffma2(P,  W[3], add2(ca[3], cb[3]));
        u64 PQ = mul2(W[0], Q2[0]);
        ffma2(PQ, W[1], Q2[1]);
        ffma2(PQ, W[2], Q2[2]);
        ffma2(PQ, W[3], Q2[3]);

        float pd = lo2(P) + hi2(P);           // dt*(sum_k w_k (A_k z + b_k)) half
        float v  = fmaf(lo2(PQ), dw, pd);     // + sqrt(dt)*noise * sum w_k Q_k half

        // cross-warp exchange: single float, parity-buffered
        pbuf[par][w][lane] = v;
        __syncthreads();
        float o = pbuf[par][w ^ 1][lane];

        zreg = (zreg + v) + o;
        zbuf[w][lane] = zreg;                 // warp-private publish (in-warp order)
        if (w == 0) yp[(size_t)si * (BB * DD)] = zreg;   // coalesced 128B
    };

    // ---- software pipeline: ping-pong A/B buffers, zero rotate movs ----
    u64 WA[2][4], WB[2][4];
    float dwA[2], dwB[2];
    pf(0, WA[0], dwA[0]);
    pf(1, WA[1], dwA[1]);
    __syncthreads();

    for (int s0 = 0; s0 < TT; s0 += 4) {
        pf(s0 + 2, WB[0], dwB[0]);
        pf(s0 + 3, WB[1], dwB[1]);
        step(s0,     WA[0], dwA[0]);
        step(s0 + 1, WA[1], dwA[1]);
        pf(s0 + 4, WA[0], dwA[0]);            // clamped past TT; unused on last iter
        pf(s0 + 5, WA[1], dwA[1]);
        step(s0 + 2, WB[0], dwB[0]);
        step(s0 + 3, WB[1], dwB[1]);
    }
}

extern "C" void kernel_launch(void* const* d_in, const int* in_sizes, int n_in,
                              void* d_out, int out_size) {
    const float* z0      = (const float*)d_in[0];
    const float* s_probs = (const float*)d_in[1];
    const float* noise   = (const float*)d_in[2];
    const float* A_s     = (const float*)d_in[3];
    const float* b_s     = (const float*)d_in[4];
    const float* Q_chol  = (const float*)d_in[5];
    float*       ys      = (float*)d_out;

    norm_kernel<<<(TT * BB + 255) / 256, 256>>>(s_probs);
    sde_main<<<BB, 64>>>(z0, noise, A_s, b_s, Q_chol, ys);
}

// round 16
// speedup vs baseline: 1.1870x; 1.1870x over previous
#include <cuda_runtime.h>
#include <cstdint>

#define TT 2048
#define BB 512
#define KK 8
#define DD 32
#define DT_F 0.05f
#define SQDT_F 0.22360679774997896f  /* sqrt(0.05) */
#define UN 4                          /* prefetch group / unroll */

typedef unsigned long long u64;

// Duplicated normalized weights: per (t,b), 16 floats (w_k, w_k) for k=0..7.
__device__ float g_wn2[(size_t)TT * BB * 16];

// ---------- f32x2 helpers ----------
__device__ __forceinline__ u64 add2(u64 a, u64 b) {
    u64 d; asm("add.rn.f32x2 %0,%1,%2;" : "=l"(d) : "l"(a), "l"(b)); return d;
}
__device__ __forceinline__ void ffma2(u64& d, u64 a, u64 b) {
    asm("fma.rn.f32x2 %0,%1,%2,%3;" : "=l"(d) : "l"(a), "l"(b), "l"(d));
}
__device__ __forceinline__ u64 ffma2_v(u64 a, u64 b, u64 c) {
    u64 d; asm("fma.rn.f32x2 %0,%1,%2,%3;" : "=l"(d) : "l"(a), "l"(b), "l"(c)); return d;
}
__device__ __forceinline__ u64 mul2(u64 a, u64 b) {
    u64 d; asm("mul.rn.f32x2 %0,%1,%2;" : "=l"(d) : "l"(a), "l"(b)); return d;
}
__device__ __forceinline__ u64 pack2(float lo, float hi) {
    u64 v; asm("mov.b64 %0,{%1,%2};" : "=l"(v) : "f"(lo), "f"(hi)); return v;
}
__device__ __forceinline__ float lo2(u64 v) { return __uint_as_float((unsigned)v); }
__device__ __forceinline__ float hi2(u64 v) { return __uint_as_float((unsigned)(v >> 32)); }

// ---------- Kernel 1: normalized weights, duplicated pairs ----------
__global__ void __launch_bounds__(256) norm_kernel(const float* __restrict__ s_probs) {
    int idx = blockIdx.x * blockDim.x + threadIdx.x;  // (t,b) pair
    if (idx < TT * BB) {
        const float4* p = (const float4*)(s_probs + (size_t)idx * KK);
        float4 a = p[0];
        float4 b = p[1];
        float s = ((a.x + a.y) + (a.z + a.w)) + ((b.x + b.y) + (b.z + b.w));
        float r = 1.0f / s;
        float4* o = (float4*)(g_wn2 + (size_t)idx * 16);
        o[0] = make_float4(a.x * r, a.x * r, a.y * r, a.y * r);
        o[1] = make_float4(a.z * r, a.z * r, a.w * r, a.w * r);
        o[2] = make_float4(b.x * r, b.x * r, b.y * r, b.y * r);
        o[3] = make_float4(b.z * r, b.z * r, b.w * r, b.w * r);
    }
}

// ---------- Kernel 2: one CTA (64 thr = 2 warps) per batch (R4 shape) ----------
// Lane i of warp wp owns row i of A_{4wp+kk} (dt-scaled). Single 16-deep FFMA2
// chain per k. Drift stays packed through the weighted combine; diffusion
// coefficient lives in the LO half ONLY (Q2 = (qs, 0)) so lo+hi counts it
// exactly once. Packed u64 cross-warp exchange. N_fma/warp-step = 76.
__global__ void __launch_bounds__(64, 4) sde_main(
    const float* __restrict__ z0,
    const float* __restrict__ noise,
    const float* __restrict__ A_s,
    const float* __restrict__ b_s,
    const float* __restrict__ Q_chol,
    float* __restrict__ ys)
{
    const int b    = blockIdx.x;
    const int tid  = threadIdx.x;
    const int w    = tid >> 5;       // 0 or 1
    const int lane = tid & 31;       // row i
    const int kb   = w * 4;          // k base

    __shared__ __align__(16) float zbuf[2][DD];   // [warp][row] private z copies
    __shared__ __align__(16) u64   pbuf[2][2][DD];// [parity][warp][row] packed v

    // ---- A rows -> registers as f32x2 pairs, pre-scaled by dt ----
    u64 A[4][16];
    u64 binit[4], Q2[4];
#pragma unroll
    for (int kk = 0; kk < 4; kk++) {
        const float4* r = (const float4*)(A_s + (size_t)((kb + kk) * DD + lane) * DD);
#pragma unroll
        for (int q = 0; q < 8; q++) {
            float4 v = r[q];
            A[kk][2 * q]     = pack2(DT_F * v.x, DT_F * v.y);
            A[kk][2 * q + 1] = pack2(DT_F * v.z, DT_F * v.w);
        }
        binit[kk] = pack2(DT_F * b_s[(kb + kk) * DD + lane], 0.0f);
        float qs  = SQDT_F * Q_chol[(kb + kk) * DD + lane];
        Q2[kk]    = pack2(qs, 0.0f);   // LO HALF ONLY (R15 bug: was (qs,qs))
    }

    // ---- z init ----
    float zreg = z0[(size_t)b * DD + lane];
    zbuf[w][lane] = zreg;

    // stream pointers (duplicated weights: 8 u64 per (t,b); warp takes 4 at kb)
    const ulonglong2* wq = (const ulonglong2*)g_wn2;    // idx = pair*4 + 2w + {0,1}
    const float*      np = noise + (size_t)b * DD + lane;
    float*            yp = ys    + (size_t)b * DD + lane;

    // ---- prefetch group 0 ----
    u64 W_c[UN][4]; float dw_c[UN];
#pragma unroll
    for (int u = 0; u < UN; u++) {
        size_t base = ((size_t)u * BB + b) * 4 + (size_t)(2 * w);
        ulonglong2 q0 = __ldg(&wq[base]);
        ulonglong2 q1 = __ldg(&wq[base + 1]);
        W_c[u][0] = q0.x; W_c[u][1] = q0.y; W_c[u][2] = q1.x; W_c[u][3] = q1.y;
        dw_c[u] = __ldg(&np[(size_t)u * (BB * DD)]);
    }

    __syncthreads();

    for (int s0 = 0; s0 < TT; s0 += UN) {
        // ---- prefetch next group (clamped; last-group values unused) ----
        u64 W_n[UN][4]; float dw_n[UN];
#pragma unroll
        for (int u = 0; u < UN; u++) {
            int ts = s0 + UN + u;
            if (ts >= TT) ts = TT - 1;
            size_t base = ((size_t)ts * BB + b) * 4 + (size_t)(2 * w);
            ulonglong2 q0 = __ldg(&wq[base]);
            ulonglong2 q1 = __ldg(&wq[base + 1]);
            W_n[u][0] = q0.x; W_n[u][1] = q0.y; W_n[u][2] = q1.x; W_n[u][3] = q1.y;
            dw_n[u] = __ldg(&np[(size_t)ts * (BB * DD)]);
        }

#pragma unroll
        for (int u = 0; u < UN; u++) {
            const int step = s0 + u;
            const int par  = step & 1;

            // ---- matvec: single 16-deep FFMA2 chain per k (4 chains) ----
            u64 acc[4];
            const ulonglong2* zv = (const ulonglong2*)(&zbuf[w][0]);
            {
                ulonglong2 z2 = zv[0];
#pragma unroll
                for (int kk = 0; kk < 4; kk++) {
                    acc[kk] = ffma2_v(A[kk][0], z2.x, binit[kk]);  // bias folded
                    ffma2(acc[kk], A[kk][1], z2.y);
                }
            }
#pragma unroll
            for (int jj = 1; jj < 8; jj++) {
                ulonglong2 z2 = zv[jj];                 // LDS.128 broadcast
#pragma unroll
                for (int kk = 0; kk < 4; kk++) {
                    ffma2(acc[kk], A[kk][2 * jj],     z2.x);
                    ffma2(acc[kk], A[kk][2 * jj + 1], z2.y);
                }
            }

            // ---- packed weighted combine (weights duplicated in memory) ----
            u64 P  = mul2(W_c[u][0], acc[0]);           // drift halves, packed
            ffma2(P,  W_c[u][1], acc[1]);
            ffma2(P,  W_c[u][2], acc[2]);
            ffma2(P,  W_c[u][3], acc[3]);
            u64 PQ = mul2(W_c[u][0], Q2[0]);            // diffusion, LO half only
            ffma2(PQ, W_c[u][1], Q2[1]);
            ffma2(PQ, W_c[u][2], Q2[2]);
            ffma2(PQ, W_c[u][3], Q2[3]);

            u64 dw2 = pack2(dw_c[u], dw_c[u]);          // MOVs (alu pipe)
            u64 v2  = ffma2_v(PQ, dw2, P);              // lo += diff*dw; hi = drift_hi

            // ---- cross-warp reduction: packed u64 exchange + 1 barrier ----
            pbuf[par][w][lane] = v2;
            __syncthreads();
            u64 o2 = pbuf[par][w ^ 1][lane];
            u64 s2 = add2(v2, o2);

            // ---- z update: 2 FADD; lo/hi are register aliases ----
            zreg = (zreg + lo2(s2)) + hi2(s2);
            zbuf[w][lane] = zreg;
            if (w == 0) yp[(size_t)step * (BB * DD)] = zreg;  // coalesced 128B
        }

        // rotate prefetch buffers
#pragma unroll
        for (int u = 0; u < UN; u++) {
            W_c[u][0] = W_n[u][0]; W_c[u][1] = W_n[u][1];
            W_c[u][2] = W_n[u][2]; W_c[u][3] = W_n[u][3];
            dw_c[u] = dw_n[u];
        }
    }
}

extern "C" void kernel_launch(void* const* d_in, const int* in_sizes, int n_in,
                              void* d_out, int out_size) {
    const float* z0      = (const float*)d_in[0];
    const float* s_probs = (const float*)d_in[1];
    const float* noise   = (const float*)d_in[2];
    const float* A_s     = (const float*)d_in[3];
    const float* b_s     = (const float*)d_in[4];
    const float* Q_chol  = (const float*)d_in[5];
    float*       ys      = (float*)d_out;

    norm_kernel<<<(TT * BB + 255) / 256, 256>>>(s_probs);
    sde_main<<<BB, 64>>>(z0, noise, A_s, b_s, Q_chol, ys);
}